// round 3
// baseline (speedup 1.0000x reference)
#include <cuda_runtime.h>
#include <math.h>

#define NT    4096
#define SEQ   128
#define DIN   32
#define DLAT  64
#define NU    256
#define INDIM 160
#define TM    32
#define NTH   512

typedef unsigned long long u64;

// ---------- packed f32x2 helpers ----------
__device__ __forceinline__ u64 bcast2(float a) {
    u64 r; asm("mov.b64 %0, {%1, %1};" : "=l"(r) : "f"(a)); return r;
}
__device__ __forceinline__ u64 pk2(float x, float y) {
    u64 r; asm("mov.b64 %0, {%1, %2};" : "=l"(r) : "f"(x), "f"(y)); return r;
}
__device__ __forceinline__ float2 unpk(u64 v) {
    float2 f; asm("mov.b64 {%0, %1}, %2;" : "=f"(f.x), "=f"(f.y) : "l"(v)); return f;
}
__device__ __forceinline__ void fma2(u64& d, u64 a, u64 b) {
    asm("fma.rn.f32x2 %0, %1, %2, %0;" : "+l"(d) : "l"(a), "l"(b));
}
__device__ __forceinline__ u64 mul2(u64 a, u64 b) {
    u64 d; asm("mul.rn.f32x2 %0, %1, %2;" : "=l"(d) : "l"(a), "l"(b)); return d;
}
__device__ __forceinline__ float sigmoid_f(float x) {
    return 1.0f / (1.0f + expf(-x));
}

// ---------- duplicated-weight scratch (u64 = {w,w}) ----------
#define OFF_Wo1 0         // 64*256   = 16384
#define OFF_Wu1 16384     // 160*256  = 40960
#define OFF_Wr1 57344
#define OFF_Wn1 98304
#define OFF_Wo2 139264    // 256*64   = 16384
#define OFF_Wu2 155648
#define OFF_Wr2 172032
#define OFF_Wn2 188416    // 256*128  = 32768
#define WD_TOTAL 221184

__device__ __align__(16) u64 g_wdup[WD_TOTAL];

__global__ void dup_all(const float* __restrict__ wo1, const float* __restrict__ wu1,
                        const float* __restrict__ wr1, const float* __restrict__ wn1,
                        const float* __restrict__ wo2, const float* __restrict__ wu2,
                        const float* __restrict__ wr2, const float* __restrict__ wn2)
{
    int i = blockIdx.x * 256 + threadIdx.x;
    if (i >= WD_TOTAL) return;
    const float* s; int off;
    if      (i < OFF_Wu1) { s = wo1; off = OFF_Wo1; }
    else if (i < OFF_Wr1) { s = wu1; off = OFF_Wu1; }
    else if (i < OFF_Wn1) { s = wr1; off = OFF_Wr1; }
    else if (i < OFF_Wo2) { s = wn1; off = OFF_Wn1; }
    else if (i < OFF_Wu2) { s = wo2; off = OFF_Wo2; }
    else if (i < OFF_Wr2) { s = wu2; off = OFF_Wu2; }
    else if (i < OFF_Wn2) { s = wr2; off = OFF_Wr2; }
    else                  { s = wn2; off = OFF_Wn2; }
    g_wdup[i] = bcast2(s[i - off]);
}

// ---------- smem layouts: pair-blocked, permuted columns (all conflict-free) ----------
// 64-col buffers (yT, lvT, uT): pair p block of 128 floats
//   scalar (c, r): p=r>>1 -> p*128 + ((c&1)*32 + (c>>1))*2 + (r&1)
#define XI(c, p)  ((p)*128 + (((c)&1)*32 + ((c)>>1))*2)
// 160-col buffers (ycT, ccT): pair block 320 floats
#define YI(c, p)  ((p)*320 + (((c)&1)*80 + ((c)>>1))*2)
// 256-col hidden buffers: pair block 512 floats, column c -> slot (c&3)*64 + (c>>2)
#define HI(c, p)  ((p)*512 + (((c)&3)*64 + ((c)>>2))*2)

struct Smem {
    float yT [16 * 128];   // 2048
    float lvT[16 * 128];
    float uT [16 * 128];
    float ycT[16 * 320];   // 5120
    float ccT[16 * 320];
    float h1A[16 * 512];   // 8192
    float h1B[16 * 512];
    float ts[SEQ];
};

// ---------- first layers: OT(h1 layout) = tanh(A^T W + b), N=256 ----------
// A in XI (COLS=64) or YI (COLS=160) layout. Wd = dup weights (u64 per elem).
template<int K, int COLS>
__device__ __forceinline__ void gemm_h1(const float* __restrict__ AT,
                                        const u64* __restrict__ Wd,
                                        const float* __restrict__ bias,
                                        float* __restrict__ OT, int tid)
{
    const int cg = tid & 63;          // 4-col group: cols 4cg..4cg+3
    const int rg = tid >> 6;          // 0..7: rows 4rg..4rg+3 (pairs 2rg, 2rg+1)
    const int pb0 = (2 * rg) * (2 * COLS);
    const int pb1 = pb0 + 2 * COLS;
    const u64* Wp = Wd + 4 * cg;

    u64 acc[2][4];
#pragma unroll
    for (int p = 0; p < 2; ++p) { acc[p][0]=0; acc[p][1]=0; acc[p][2]=0; acc[p][3]=0; }

#pragma unroll 2
    for (int t = 0; t < K / 2; ++t) {
#pragma unroll
        for (int jj = 0; jj < 2; ++jj) {
            const int k = 2 * t + jj;
            const int m = (jj * (COLS / 2) + t) * 2;
            u64 a0 = *reinterpret_cast<const u64*>(AT + pb0 + m);
            u64 a1 = *reinterpret_cast<const u64*>(AT + pb1 + m);
            ulonglong2 wA = *reinterpret_cast<const ulonglong2*>(Wp + (size_t)k * 256);
            ulonglong2 wB = *reinterpret_cast<const ulonglong2*>(Wp + (size_t)k * 256 + 2);
            fma2(acc[0][0], a0, wA.x); fma2(acc[0][1], a0, wA.y);
            fma2(acc[0][2], a0, wB.x); fma2(acc[0][3], a0, wB.y);
            fma2(acc[1][0], a1, wA.x); fma2(acc[1][1], a1, wA.y);
            fma2(acc[1][2], a1, wB.x); fma2(acc[1][3], a1, wB.y);
        }
    }
    float4 b4 = reinterpret_cast<const float4*>(bias)[cg];
    float bb[4] = {b4.x, b4.y, b4.z, b4.w};
#pragma unroll
    for (int p = 0; p < 2; ++p)
#pragma unroll
        for (int j = 0; j < 4; ++j) {
            float2 v = unpk(acc[p][j]);
            v.x = tanhf(v.x + bb[j]);
            v.y = tanhf(v.y + bb[j]);
            // col 4cg+j -> h1 slot j*64+cg, pair 2rg+p  (contiguous across warp)
            *reinterpret_cast<u64*>(OT + (2 * rg + p) * 512 + (j * 64 + cg) * 2) = pk2(v.x, v.y);
        }
}

// ---------- second layer core: K=256 from h1 layout, 2 cols x 1 row-pair ----------
__device__ __forceinline__ void gemm64_acc(const float* __restrict__ Ab,  // + rp*512
                                           const u64* __restrict__ Wd,    // + 2*cp
                                           u64& acc0, u64& acc1)
{
    acc0 = 0; acc1 = 0;
#pragma unroll 2
    for (int t = 0; t < 64; ++t) {
#pragma unroll
        for (int j = 0; j < 4; ++j) {
            u64 a2 = *reinterpret_cast<const u64*>(Ab + (j * 64 + t) * 2);
            ulonglong2 w = *reinterpret_cast<const ulonglong2*>(Wd + (size_t)(4 * t + j) * 64);
            fma2(acc0, a2, w.x);
            fma2(acc1, a2, w.y);
        }
    }
}

__global__ __launch_bounds__(NTH, 1)
void ode_rnn_kernel(const float* __restrict__ data,
                    const float* __restrict__ tsteps,
                    const float* __restrict__ bo1, const float* __restrict__ bo2,
                    const float* __restrict__ bu1, const float* __restrict__ bu2,
                    const float* __restrict__ br1, const float* __restrict__ br2,
                    const float* __restrict__ bn1, const float* __restrict__ bn2,
                    float* __restrict__ out)
{
    extern __shared__ float smem_raw[];
    Smem* S = reinterpret_cast<Smem*>(smem_raw);
    const int tid = threadIdx.x;
    const int traj0 = blockIdx.x * TM;

    const int cp = tid & 31;   // col-pair index for 64-wide stages
    const int rp = tid >> 5;   // row-pair 0..15

    for (int i = tid; i < 16 * 128; i += NTH) { S->yT[i] = 0.f; S->lvT[i] = 0.f; }
    for (int i = tid; i < SEQ; i += NTH) S->ts[i] = tsteps[i];
    __syncthreads();

    for (int s = 0; s < SEQ - 1; ++s) {
        const float dt = (s == 0) ? (S->ts[1] - S->ts[0]) : (S->ts[s] - S->ts[s + 1]);

        // ===== A: stage lv -> ycT[64:128], x -> ycT/ccT[128:160]; ODE L1 =====
#pragma unroll
        for (int j = 0; j < 2; ++j) {
            int c = 2 * cp + j;
            u64 v = *reinterpret_cast<const u64*>(S->lvT + XI(c, rp));
            *reinterpret_cast<u64*>(S->ycT + YI(c + DLAT, rp)) = v;
        }
#pragma unroll
        for (int e = 0; e < 2; ++e) {
            int idx = tid + e * NTH;          // 0..1023
            int r = idx >> 5, c = idx & 31;
            float v = data[(size_t)(traj0 + r) * SEQ * DIN + (size_t)(s + 1) * DIN + c];
            int a = YI(2 * DLAT + c, r >> 1) + (r & 1);
            S->ycT[a] = v;
            S->ccT[a] = v;
        }
        gemm_h1<DLAT, DLAT>(S->yT, g_wdup + OFF_Wo1, bo1, S->h1A, tid);
        __syncthreads();

        // ===== B: ODE L2 -> ycT[0:64] =====
        {
            u64 a0, a1;
            gemm64_acc(S->h1A + rp * 512, g_wdup + OFF_Wo2 + 2 * cp, a0, a1);
            float2 bb = *reinterpret_cast<const float2*>(bo2 + 2 * cp);
            float bj[2] = {bb.x, bb.y};
            u64 accs[2] = {a0, a1};
#pragma unroll
            for (int j = 0; j < 2; ++j) {
                int c = 2 * cp + j;
                float2 o = unpk(accs[j]);
                float2 y = unpk(*reinterpret_cast<const u64*>(S->yT + XI(c, rp)));
                float2 r;
                r.x = fmaf(o.x + bj[j], dt, y.x);
                r.y = fmaf(o.y + bj[j], dt, y.y);
                *reinterpret_cast<u64*>(S->ycT + YI(c, rp)) = pk2(r.x, r.y);
            }
        }
        __syncthreads();

        // ===== C: update-gate L1 -> h1A ; reset-gate L1 -> h1B =====
        gemm_h1<INDIM, INDIM>(S->ycT, g_wdup + OFF_Wu1, bu1, S->h1A, tid);
        gemm_h1<INDIM, INDIM>(S->ycT, g_wdup + OFF_Wr1, br1, S->h1B, tid);
        __syncthreads();

        // ===== D: update-gate L2 -> uT ; reset-gate L2 -> ccT[0:128] =====
        {
            u64 a0, a1;
            gemm64_acc(S->h1A + rp * 512, g_wdup + OFF_Wu2 + 2 * cp, a0, a1);
            float2 bb = *reinterpret_cast<const float2*>(bu2 + 2 * cp);
            float2 v0 = unpk(a0), v1 = unpk(a1);
            *reinterpret_cast<u64*>(S->uT + XI(2 * cp, rp)) =
                pk2(sigmoid_f(v0.x + bb.x), sigmoid_f(v0.y + bb.x));
            *reinterpret_cast<u64*>(S->uT + XI(2 * cp + 1, rp)) =
                pk2(sigmoid_f(v1.x + bb.y), sigmoid_f(v1.y + bb.y));
        }
        {
            u64 a0, a1;
            gemm64_acc(S->h1B + rp * 512, g_wdup + OFF_Wr2 + 2 * cp, a0, a1);
            float2 bb = *reinterpret_cast<const float2*>(br2 + 2 * cp);
            float bj[2] = {bb.x, bb.y};
            u64 accs[2] = {a0, a1};
#pragma unroll
            for (int j = 0; j < 2; ++j) {
                int c = 2 * cp + j;
                float2 v = unpk(accs[j]);
                u64 rpair = pk2(sigmoid_f(v.x + bj[j]), sigmoid_f(v.y + bj[j]));
                u64 ylo = *reinterpret_cast<const u64*>(S->ycT + YI(c, rp));
                u64 yhi = *reinterpret_cast<const u64*>(S->ycT + YI(c + DLAT, rp));
                *reinterpret_cast<u64*>(S->ccT + YI(c, rp))        = mul2(ylo, rpair);
                *reinterpret_cast<u64*>(S->ccT + YI(c + DLAT, rp)) = mul2(yhi, rpair);
            }
        }
        __syncthreads();

        // ===== E: candidate L1 -> h1A =====
        gemm_h1<INDIM, INDIM>(S->ccT, g_wdup + OFF_Wn1, bn1, S->h1A, tid);
        __syncthreads();

        // ===== F: candidate L2 (N=128) + fused state update =====
        {
            u64 aS0 = 0, aS1 = 0, aD0 = 0, aD1 = 0;
            const float* Ab = S->h1A + rp * 512;
            const u64* WpL = g_wdup + OFF_Wn2 + 2 * cp;
            const u64* WpH = WpL + DLAT;
#pragma unroll 2
            for (int t = 0; t < 64; ++t) {
#pragma unroll
                for (int j = 0; j < 4; ++j) {
                    u64 a2 = *reinterpret_cast<const u64*>(Ab + (j * 64 + t) * 2);
                    ulonglong2 wl = *reinterpret_cast<const ulonglong2*>(WpL + (size_t)(4 * t + j) * 128);
                    ulonglong2 wh = *reinterpret_cast<const ulonglong2*>(WpH + (size_t)(4 * t + j) * 128);
                    fma2(aS0, a2, wl.x); fma2(aS1, a2, wl.y);
                    fma2(aD0, a2, wh.x); fma2(aD1, a2, wh.y);
                }
            }
            float2 bl = *reinterpret_cast<const float2*>(bn2 + 2 * cp);
            float2 bh = *reinterpret_cast<const float2*>(bn2 + DLAT + 2 * cp);
            float blj[2] = {bl.x, bl.y};
            float bhj[2] = {bh.x, bh.y};
            u64 accS[2] = {aS0, aS1};
            u64 accD[2] = {aD0, aD1};
#pragma unroll
            for (int j = 0; j < 2; ++j) {
                int c = 2 * cp + j;
                float2 ns = unpk(accS[j]);
                ns.x += blj[j]; ns.y += blj[j];
                float2 nd = unpk(accD[j]);
                nd.x = fabsf(nd.x + bhj[j]); nd.y = fabsf(nd.y + bhj[j]);
                float2 uu = unpk(*reinterpret_cast<const u64*>(S->uT + XI(c, rp)));
                float2 yo = unpk(*reinterpret_cast<const u64*>(S->ycT + YI(c, rp)));
                float2 lo = unpk(*reinterpret_cast<const u64*>(S->lvT + XI(c, rp)));
                float ny0 = (1.f - uu.x) * ns.x + uu.x * yo.x;
                float ny1 = (1.f - uu.y) * ns.y + uu.y * yo.y;
                float nl0 = (1.f - uu.x) * nd.x + uu.x * lo.x;
                float nl1 = (1.f - uu.y) * nd.y + uu.y * lo.y;
                *reinterpret_cast<u64*>(S->yT + XI(c, rp))  = pk2(ny0, ny1);
                *reinterpret_cast<u64*>(S->lvT + XI(c, rp)) = pk2(nl0, nl1);
            }
        }
        __syncthreads();
    }

    // ===== output: yi (4096x64) then yi_logvar (4096x64) =====
    for (int i = tid; i < TM * DLAT; i += NTH) {
        int r = i >> 6, c = i & 63;
        int a = XI(c, r >> 1) + (r & 1);
        out[(size_t)(traj0 + r) * DLAT + c] = S->yT[a];
        out[(size_t)NT * DLAT + (size_t)(traj0 + r) * DLAT + c] = S->lvT[a];
    }
}

extern "C" void kernel_launch(void* const* d_in, const int* in_sizes, int n_in,
                              void* d_out, int out_size) {
    const float* data = (const float*)d_in[0];
    const float* ts   = (const float*)d_in[1];
    const float* Wo1  = (const float*)d_in[2];
    const float* bo1  = (const float*)d_in[3];
    const float* Wo2  = (const float*)d_in[4];
    const float* bo2  = (const float*)d_in[5];
    const float* Wu1  = (const float*)d_in[6];
    const float* bu1  = (const float*)d_in[7];
    const float* Wu2  = (const float*)d_in[8];
    const float* bu2  = (const float*)d_in[9];
    const float* Wr1  = (const float*)d_in[10];
    const float* br1  = (const float*)d_in[11];
    const float* Wr2  = (const float*)d_in[12];
    const float* br2  = (const float*)d_in[13];
    const float* Wn1  = (const float*)d_in[14];
    const float* bn1  = (const float*)d_in[15];
    const float* Wn2  = (const float*)d_in[16];
    const float* bn2  = (const float*)d_in[17];
    float* out = (float*)d_out;

    dup_all<<<(WD_TOTAL + 255) / 256, 256>>>(Wo1, Wu1, Wr1, Wn1, Wo2, Wu2, Wr2, Wn2);

    const int smem = (int)sizeof(Smem);
    cudaFuncSetAttribute(ode_rnn_kernel,
                         cudaFuncAttributeMaxDynamicSharedMemorySize, smem);
    ode_rnn_kernel<<<NT / TM, NTH, smem>>>(
        data, ts, bo1, bo2, bu1, bu2, br1, br2, bn1, bn2, out);
}

// round 5
// speedup vs baseline: 1.7674x; 1.7674x over previous
#include <cuda_runtime.h>
#include <math.h>

#define NT    4096
#define SEQ   128
#define DIN   32
#define DLAT  64
#define NU    256
#define INDIM 160
#define TM    32
#define NTH   512

typedef unsigned long long u64;

// ---------- packed f32x2 helpers ----------
__device__ __forceinline__ u64 bcast2(float a) {
    u64 r; asm("mov.b64 %0, {%1, %1};" : "=l"(r) : "f"(a)); return r;
}
__device__ __forceinline__ u64 pk2(float x, float y) {
    u64 r; asm("mov.b64 %0, {%1, %2};" : "=l"(r) : "f"(x), "f"(y)); return r;
}
__device__ __forceinline__ float2 unpk(u64 v) {
    float2 f; asm("mov.b64 {%0, %1}, %2;" : "=f"(f.x), "=f"(f.y) : "l"(v)); return f;
}
__device__ __forceinline__ void fma2(u64& d, u64 a, u64 b) {
    asm("fma.rn.f32x2 %0, %1, %2, %0;" : "+l"(d) : "l"(a), "l"(b));
}
__device__ __forceinline__ u64 mul2(u64 a, u64 b) {
    u64 d; asm("mul.rn.f32x2 %0, %1, %2;" : "=l"(d) : "l"(a), "l"(b)); return d;
}
__device__ __forceinline__ float sigmoid_f(float x) {
    return 1.0f / (1.0f + expf(-x));
}

// ---------- smem layouts: pair-blocked, permuted columns (conflict-free) ----------
// 64-col buffers: pair p block of 128 floats
#define XI(c, p)  ((p)*128 + (((c)&1)*32 + ((c)>>1))*2)
// 160-col buffers: pair block 320 floats
#define YI(c, p)  ((p)*320 + (((c)&1)*80 + ((c)>>1))*2)
// 256-col hidden buffers: pair block 512 floats, col c -> slot (c&3)*64 + (c>>2)

struct Smem {
    float yT [16 * 128];
    float lvT[16 * 128];
    float uT [16 * 128];
    float ycT[16 * 320];
    float ccT[16 * 320];
    float h1A[16 * 512];
    float h1B[16 * 512];
    float ts[SEQ];
};

// ---------- first layers: OT(h1 layout) = tanh(A^T W + b), N=256 ----------
// A in XI (COLS=64) or YI (COLS=160) layout. W: gmem row-major [K][256].
template<int K, int COLS>
__device__ __forceinline__ void gemm_h1(const float* __restrict__ AT,
                                        const float* __restrict__ W,
                                        const float* __restrict__ bias,
                                        float* __restrict__ OT, int tid)
{
    const int cg = tid & 63;          // cols 4cg..4cg+3
    const int rg = tid >> 6;          // 0..7: pairs 2rg, 2rg+1
    const int pb0 = (2 * rg) * (2 * COLS);
    const int pb1 = pb0 + 2 * COLS;
    const float4* W4 = reinterpret_cast<const float4*>(W) + cg;

    u64 acc[2][4];
#pragma unroll
    for (int p = 0; p < 2; ++p) { acc[p][0]=0; acc[p][1]=0; acc[p][2]=0; acc[p][3]=0; }

#pragma unroll 4
    for (int k = 0; k < K; ++k) {
        float4 w = W4[(size_t)k * (NU / 4)];
        u64 w0 = bcast2(w.x), w1 = bcast2(w.y), w2 = bcast2(w.z), w3 = bcast2(w.w);
        const int m = ((k & 1) * (COLS / 2) + (k >> 1)) * 2;
        u64 a0 = *reinterpret_cast<const u64*>(AT + pb0 + m);
        u64 a1 = *reinterpret_cast<const u64*>(AT + pb1 + m);
        fma2(acc[0][0], a0, w0); fma2(acc[0][1], a0, w1);
        fma2(acc[0][2], a0, w2); fma2(acc[0][3], a0, w3);
        fma2(acc[1][0], a1, w0); fma2(acc[1][1], a1, w1);
        fma2(acc[1][2], a1, w2); fma2(acc[1][3], a1, w3);
    }
    float4 b4 = reinterpret_cast<const float4*>(bias)[cg];
    float bb[4] = {b4.x, b4.y, b4.z, b4.w};
#pragma unroll
    for (int p = 0; p < 2; ++p)
#pragma unroll
        for (int j = 0; j < 4; ++j) {
            float2 v = unpk(acc[p][j]);
            v.x = tanhf(v.x + bb[j]);
            v.y = tanhf(v.y + bb[j]);
            *reinterpret_cast<u64*>(OT + (2 * rg + p) * 512 + (j * 64 + cg) * 2) = pk2(v.x, v.y);
        }
}

// ---------- second-layer core: K=256 from h1 layout, 2 cols x 1 row-pair ----------
// W: gmem row-major [256][64]; cols 2cp, 2cp+1; A base = h1 + rp*512
__device__ __forceinline__ void gemm64_acc(const float* __restrict__ Ab,
                                           const float* __restrict__ W,
                                           int cp, u64& acc0, u64& acc1)
{
    acc0 = 0; acc1 = 0;
    const float2* W2 = reinterpret_cast<const float2*>(W) + cp;
#pragma unroll 4
    for (int t = 0; t < 64; ++t) {
#pragma unroll
        for (int j = 0; j < 4; ++j) {
            u64 a2 = *reinterpret_cast<const u64*>(Ab + (j * 64 + t) * 2);
            float2 w = W2[(size_t)(4 * t + j) * 32];
            fma2(acc0, a2, bcast2(w.x));
            fma2(acc1, a2, bcast2(w.y));
        }
    }
}

__global__ __launch_bounds__(NTH, 1)
void ode_rnn_kernel(const float* __restrict__ data,
                    const float* __restrict__ tsteps,
                    const float* __restrict__ Wo1, const float* __restrict__ bo1,
                    const float* __restrict__ Wo2, const float* __restrict__ bo2,
                    const float* __restrict__ Wu1, const float* __restrict__ bu1,
                    const float* __restrict__ Wu2, const float* __restrict__ bu2,
                    const float* __restrict__ Wr1, const float* __restrict__ br1,
                    const float* __restrict__ Wr2, const float* __restrict__ br2,
                    const float* __restrict__ Wn1, const float* __restrict__ bn1,
                    const float* __restrict__ Wn2, const float* __restrict__ bn2,
                    float* __restrict__ out)
{
    extern __shared__ float smem_raw[];
    Smem* S = reinterpret_cast<Smem*>(smem_raw);
    const int tid = threadIdx.x;
    const int traj0 = blockIdx.x * TM;

    const int cp = tid & 31;   // col-pair for 64-wide stages
    const int rp = tid >> 5;   // row-pair 0..15

    for (int i = tid; i < 16 * 128; i += NTH) { S->yT[i] = 0.f; S->lvT[i] = 0.f; }
    for (int i = tid; i < SEQ; i += NTH) S->ts[i] = tsteps[i];
    __syncthreads();

    for (int s = 0; s < SEQ - 1; ++s) {
        const float dt = (s == 0) ? (S->ts[1] - S->ts[0]) : (S->ts[s] - S->ts[s + 1]);

        // ===== A: stage lv -> ycT[64:128], x -> ycT/ccT[128:160]; ODE L1 =====
#pragma unroll
        for (int j = 0; j < 2; ++j) {
            int c = 2 * cp + j;
            u64 v = *reinterpret_cast<const u64*>(S->lvT + XI(c, rp));
            *reinterpret_cast<u64*>(S->ycT + YI(c + DLAT, rp)) = v;
        }
#pragma unroll
        for (int e = 0; e < 2; ++e) {
            int idx = tid + e * NTH;          // 0..1023
            int r = idx >> 5, c = idx & 31;
            float v = data[(size_t)(traj0 + r) * SEQ * DIN + (size_t)(s + 1) * DIN + c];
            int a = YI(2 * DLAT + c, r >> 1) + (r & 1);
            S->ycT[a] = v;
            S->ccT[a] = v;
        }
        gemm_h1<DLAT, DLAT>(S->yT, Wo1, bo1, S->h1A, tid);
        __syncthreads();

        // ===== B: ODE L2 -> ycT[0:64] =====
        {
            u64 a0, a1;
            gemm64_acc(S->h1A + rp * 512, Wo2, cp, a0, a1);
            float2 bb = *reinterpret_cast<const float2*>(bo2 + 2 * cp);
            float bj[2] = {bb.x, bb.y};
            u64 accs[2] = {a0, a1};
#pragma unroll
            for (int j = 0; j < 2; ++j) {
                int c = 2 * cp + j;
                float2 o = unpk(accs[j]);
                float2 y = unpk(*reinterpret_cast<const u64*>(S->yT + XI(c, rp)));
                float2 r;
                r.x = fmaf(o.x + bj[j], dt, y.x);
                r.y = fmaf(o.y + bj[j], dt, y.y);
                *reinterpret_cast<u64*>(S->ycT + YI(c, rp)) = pk2(r.x, r.y);
            }
        }
        __syncthreads();

        // ===== C: update-gate L1 -> h1A ; reset-gate L1 -> h1B =====
        gemm_h1<INDIM, INDIM>(S->ycT, Wu1, bu1, S->h1A, tid);
        gemm_h1<INDIM, INDIM>(S->ycT, Wr1, br1, S->h1B, tid);
        __syncthreads();

        // ===== D: update-gate L2 -> uT ; reset-gate L2 -> ccT[0:128] =====
        {
            u64 a0, a1;
            gemm64_acc(S->h1A + rp * 512, Wu2, cp, a0, a1);
            float2 bb = *reinterpret_cast<const float2*>(bu2 + 2 * cp);
            float2 v0 = unpk(a0), v1 = unpk(a1);
            *reinterpret_cast<u64*>(S->uT + XI(2 * cp, rp)) =
                pk2(sigmoid_f(v0.x + bb.x), sigmoid_f(v0.y + bb.x));
            *reinterpret_cast<u64*>(S->uT + XI(2 * cp + 1, rp)) =
                pk2(sigmoid_f(v1.x + bb.y), sigmoid_f(v1.y + bb.y));
        }
        {
            u64 a0, a1;
            gemm64_acc(S->h1B + rp * 512, Wr2, cp, a0, a1);
            float2 bb = *reinterpret_cast<const float2*>(br2 + 2 * cp);
            float bj[2] = {bb.x, bb.y};
            u64 accs[2] = {a0, a1};
#pragma unroll
            for (int j = 0; j < 2; ++j) {
                int c = 2 * cp + j;
                float2 v = unpk(accs[j]);
                u64 rpair = pk2(sigmoid_f(v.x + bj[j]), sigmoid_f(v.y + bj[j]));
                u64 ylo = *reinterpret_cast<const u64*>(S->ycT + YI(c, rp));
                u64 yhi = *reinterpret_cast<const u64*>(S->ycT + YI(c + DLAT, rp));
                *reinterpret_cast<u64*>(S->ccT + YI(c, rp))        = mul2(ylo, rpair);
                *reinterpret_cast<u64*>(S->ccT + YI(c + DLAT, rp)) = mul2(yhi, rpair);
            }
        }
        __syncthreads();

        // ===== E: candidate L1 -> h1A =====
        gemm_h1<INDIM, INDIM>(S->ccT, Wn1, bn1, S->h1A, tid);
        __syncthreads();

        // ===== F: candidate L2 (N=128) + fused state update =====
        {
            u64 aS0 = 0, aS1 = 0, aD0 = 0, aD1 = 0;
            const float* Ab = S->h1A + rp * 512;
            const float2* WL = reinterpret_cast<const float2*>(Wn2) + cp;        // cols 2cp,2cp+1
            const float2* WH = WL + 32;                                          // cols 64+2cp,..
#pragma unroll 4
            for (int t = 0; t < 64; ++t) {
#pragma unroll
                for (int j = 0; j < 4; ++j) {
                    u64 a2 = *reinterpret_cast<const u64*>(Ab + (j * 64 + t) * 2);
                    float2 wl = WL[(size_t)(4 * t + j) * 64];
                    float2 wh = WH[(size_t)(4 * t + j) * 64];
                    fma2(aS0, a2, bcast2(wl.x)); fma2(aS1, a2, bcast2(wl.y));
                    fma2(aD0, a2, bcast2(wh.x)); fma2(aD1, a2, bcast2(wh.y));
                }
            }
            float2 bl = *reinterpret_cast<const float2*>(bn2 + 2 * cp);
            float2 bh = *reinterpret_cast<const float2*>(bn2 + DLAT + 2 * cp);
            float blj[2] = {bl.x, bl.y};
            float bhj[2] = {bh.x, bh.y};
            u64 accS[2] = {aS0, aS1};
            u64 accD[2] = {aD0, aD1};
#pragma unroll
            for (int j = 0; j < 2; ++j) {
                int c = 2 * cp + j;
                float2 ns = unpk(accS[j]);
                ns.x += blj[j]; ns.y += blj[j];
                float2 nd = unpk(accD[j]);
                nd.x = fabsf(nd.x + bhj[j]); nd.y = fabsf(nd.y + bhj[j]);
                float2 uu = unpk(*reinterpret_cast<const u64*>(S->uT + XI(c, rp)));
                float2 yo = unpk(*reinterpret_cast<const u64*>(S->ycT + YI(c, rp)));
                float2 lo = unpk(*reinterpret_cast<const u64*>(S->lvT + XI(c, rp)));
                float ny0 = (1.f - uu.x) * ns.x + uu.x * yo.x;
                float ny1 = (1.f - uu.y) * ns.y + uu.y * yo.y;
                float nl0 = (1.f - uu.x) * nd.x + uu.x * lo.x;
                float nl1 = (1.f - uu.y) * nd.y + uu.y * lo.y;
                *reinterpret_cast<u64*>(S->yT + XI(c, rp))  = pk2(ny0, ny1);
                *reinterpret_cast<u64*>(S->lvT + XI(c, rp)) = pk2(nl0, nl1);
            }
        }
        __syncthreads();
    }

    // ===== output: yi (4096x64) then yi_logvar (4096x64) =====
    for (int i = tid; i < TM * DLAT; i += NTH) {
        int r = i >> 6, c = i & 63;
        int a = XI(c, r >> 1) + (r & 1);
        out[(size_t)(traj0 + r) * DLAT + c] = S->yT[a];
        out[(size_t)NT * DLAT + (size_t)(traj0 + r) * DLAT + c] = S->lvT[a];
    }
}

extern "C" void kernel_launch(void* const* d_in, const int* in_sizes, int n_in,
                              void* d_out, int out_size) {
    const float* data = (const float*)d_in[0];
    const float* ts   = (const float*)d_in[1];
    const float* Wo1  = (const float*)d_in[2];
    const float* bo1  = (const float*)d_in[3];
    const float* Wo2  = (const float*)d_in[4];
    const float* bo2  = (const float*)d_in[5];
    const float* Wu1  = (const float*)d_in[6];
    const float* bu1  = (const float*)d_in[7];
    const float* Wu2  = (const float*)d_in[8];
    const float* bu2  = (const float*)d_in[9];
    const float* Wr1  = (const float*)d_in[10];
    const float* br1  = (const float*)d_in[11];
    const float* Wr2  = (const float*)d_in[12];
    const float* br2  = (const float*)d_in[13];
    const float* Wn1  = (const float*)d_in[14];
    const float* bn1  = (const float*)d_in[15];
    const float* Wn2  = (const float*)d_in[16];
    const float* bn2  = (const float*)d_in[17];
    float* out = (float*)d_out;

    const int smem = (int)sizeof(Smem);
    cudaFuncSetAttribute(ode_rnn_kernel,
                         cudaFuncAttributeMaxDynamicSharedMemorySize, smem);
    ode_rnn_kernel<<<NT / TM, NTH, smem>>>(
        data, ts, Wo1, bo1, Wo2, bo2, Wu1, bu1, Wu2, bu2,
        Wr1, br1, Wr2, br2, Wn1, bn1, Wn2, bn2, out);
}